// round 14
// baseline (speedup 1.0000x reference)
#include <cuda_runtime.h>

#define B_SZ 256
#define T_SZ 2000
#define F_SZ 128

#define T_MAIN  1728               // timesteps streamed by fused blocks (27*64)
#define T_TAIL  (T_SZ - T_MAIN)    // 272, streamed by helper blocks
#define CHUNK   64
#define NCHUNK_MAIN (T_MAIN / CHUNK)   // 27
#define NBUF    8
#define DOT_WARPS 8
#define T_PER_WARP 8
#define THREADS 288                // 9 warps

#define HELP_BLOCKS 40
#define NSLICE  (T_TAIL / 8)       // 34 slices of 8 ts per row
#define NUNIT   (B_SZ * NSLICE)    // 8704
#define HWARPS  (HELP_BLOCKS * 9)  // 360

// BETA = sigmoid(2.0), VTH = 1.0
#define BETA_F 0.8807970779778823f

// tail scratch (device globals, zero-init; counters reset by consumer)
__device__ float g_cur2[B_SZ * T_TAIL];
__device__ int   g_cnt[B_SZ * NSLICE];   // target 4 per slice

#define BAR_FULL(i)  ((i) & 7)
#define BAR_EMPTY(i) (8 + ((i) & 7))

__device__ __forceinline__ void bar_sync(int id) {
    asm volatile("bar.sync %0, %1;" :: "r"(id), "n"(THREADS) : "memory");
}
__device__ __forceinline__ void bar_arrive(int id) {
    asm volatile("bar.arrive %0, %1;" :: "r"(id), "n"(THREADS) : "memory");
}
static __device__ __forceinline__ int ld_acquire(const int* p) {
    int v;
    asm volatile("ld.acquire.gpu.global.s32 %0, [%1];"
                 : "=r"(v) : "l"(p) : "memory");
    return v;
}
static __device__ __forceinline__ void red_release_add(int* p, int v) {
    asm volatile("red.release.gpu.global.add.s32 [%0], %1;"
                 :: "l"(p), "r"(v) : "memory");
}

__device__ __forceinline__ float lif_step(float& v, float c) {
    float u = fmaf(BETA_F, v, c);
    float w = u - 1.0f;
    bool  p = (u >= 1.0f);
    v = p ? w : u;
    return p ? 1.0f : 0.0f;
}

__global__ void __launch_bounds__(THREADS, 2) lif_fused_kernel(
    const float* __restrict__ x, const float* __restrict__ W,
    const float* __restrict__ bias, float* __restrict__ out, int out_size)
{
    __shared__ float cur_s[NBUF][CHUNK];

    const int wid  = threadIdx.x >> 5;
    const int lane = threadIdx.x & 31;
    const int sub  = lane & 7;
    const int grp  = lane >> 3;

    if (blockIdx.x >= B_SZ) {
        // ================= helper blocks: stream the tail =================
        float4 w4[4];
        #pragma unroll
        for (int j = 0; j < 4; ++j)
            w4[j] = reinterpret_cast<const float4*>(W)[sub + 8 * j];
        const float bias_v = bias[0];
        const float4* X4 = reinterpret_cast<const float4*>(x);

        const int wg = (blockIdx.x - B_SZ) * 9 + wid;
        for (int u = wg; u < NUNIT; u += HWARPS) {
            const int row = u / NSLICE;
            const int sl  = u - row * NSLICE;
            const int t0  = T_MAIN + sl * 8;
            const float4* xp = X4 + ((size_t)row * T_SZ + t0) * (F_SZ / 4);

            // batch all 8 LDG.128 (4KB in flight)
            float4 xv[2][4];
            #pragma unroll
            for (int p = 0; p < 2; ++p)
                #pragma unroll
                for (int j = 0; j < 4; ++j)
                    xv[p][j] = xp[(p * 4 + grp) * (F_SZ / 4) + sub + 8 * j];

            #pragma unroll
            for (int p = 0; p < 2; ++p) {
                float s = 0.0f;
                #pragma unroll
                for (int j = 0; j < 4; ++j) {
                    s = fmaf(xv[p][j].x, w4[j].x, s);
                    s = fmaf(xv[p][j].y, w4[j].y, s);
                    s = fmaf(xv[p][j].z, w4[j].z, s);
                    s = fmaf(xv[p][j].w, w4[j].w, s);
                }
                s += __shfl_xor_sync(0xFFFFFFFFu, s, 4);
                s += __shfl_xor_sync(0xFFFFFFFFu, s, 2);
                s += __shfl_xor_sync(0xFFFFFFFFu, s, 1);
                if (sub == 0)
                    g_cur2[row * T_TAIL + sl * 8 + p * 4 + grp] = s + bias_v;
            }
            // each storing lane (4 of them) releases once: target 4/slice
            if (sub == 0)
                red_release_add(&g_cnt[row * NSLICE + sl], 1);
        }
        return;
    }

    // ===================== fused blocks (rows) =====================
    const int b = blockIdx.x;

    if (wid > 0) {
        // ---------- producers: dot warps 1..8 (R12, T_MAIN only) ----------
        float4 w4[4];
        #pragma unroll
        for (int j = 0; j < 4; ++j)
            w4[j] = reinterpret_cast<const float4*>(W)[sub + 8 * j];
        const float bias_v = bias[0];

        const int slice0 = (wid - 1) * T_PER_WARP;
        const float4* X4 = reinterpret_cast<const float4*>(
            x + (size_t)b * T_SZ * F_SZ);

        auto load_batch = [&](float4 (&dst)[2][4], int c) {
            const int t0 = c * CHUNK + slice0;
            #pragma unroll
            for (int p = 0; p < 2; ++p) {
                int trow = t0 + p * 4 + grp;
                trow = (trow < T_MAIN) ? trow : (T_MAIN - 1);   // clamp
                const float4* rp = X4 + (size_t)trow * (F_SZ / 4) + sub;
                #pragma unroll
                for (int j = 0; j < 4; ++j)
                    dst[p][j] = rp[8 * j];
            }
        };

        auto reduce_store = [&](const float4 (&src)[2][4], int c) {
            const int buf = c & (NBUF - 1);
            const int t0  = c * CHUNK + slice0;
            #pragma unroll
            for (int p = 0; p < 2; ++p) {
                float s = 0.0f;
                #pragma unroll
                for (int j = 0; j < 4; ++j) {
                    s = fmaf(src[p][j].x, w4[j].x, s);
                    s = fmaf(src[p][j].y, w4[j].y, s);
                    s = fmaf(src[p][j].z, w4[j].z, s);
                    s = fmaf(src[p][j].w, w4[j].w, s);
                }
                s += __shfl_xor_sync(0xFFFFFFFFu, s, 4);
                s += __shfl_xor_sync(0xFFFFFFFFu, s, 2);
                s += __shfl_xor_sync(0xFFFFFFFFu, s, 1);
                const int trow = t0 + p * 4 + grp;
                if (sub == 0 && trow < T_MAIN)
                    cur_s[buf][trow - c * CHUNK] = s + bias_v;
            }
        };

        float4 xv[2][4];
        float4 xn[2][4];
        load_batch(xv, 0);

        #pragma unroll 1
        for (int c = 0; c < NCHUNK_MAIN; c += 2) {   // pairs (0,1)..(26,27)
            load_batch(xn, c + 1);
            bar_sync(BAR_EMPTY(c));
            reduce_store(xv, c);
            bar_arrive(BAR_FULL(c));

            const int c2 = (c + 2 < NCHUNK_MAIN) ? c + 2 : NCHUNK_MAIN - 1;
            load_batch(xv, c2);
            bar_sync(BAR_EMPTY(c + 1));
            reduce_store(xn, c + 1);
            bar_arrive(BAR_FULL(c + 1));
        }
    } else {
        // ---------- consumer: scan warp 0 ----------
        #pragma unroll
        for (int i = 0; i < NBUF; ++i)
            bar_arrive(BAR_EMPTY(i));

        float v = 0.0f;
        float* out_row = out + (size_t)b * T_SZ;

        // main region: 27 full chunks from the smem ring
        for (int c = 0; c < NCHUNK_MAIN; ++c) {
            bar_sync(BAR_FULL(c));

            if (lane == 0) {
                const int buf = c & (NBUF - 1);
                const float4* cs = reinterpret_cast<const float4*>(&cur_s[buf][0]);
                float4* op = reinterpret_cast<float4*>(out_row + c * CHUNK);

                float4 cu = cs[0];
                #pragma unroll 4
                for (int g = 0; g < CHUNK / 4; ++g) {
                    float4 nxt = cu;
                    if (g + 1 < CHUNK / 4) nxt = cs[g + 1];
                    float s0 = lif_step(v, cu.x);
                    float s1 = lif_step(v, cu.y);
                    float s2 = lif_step(v, cu.z);
                    float s3 = lif_step(v, cu.w);
                    op[g] = make_float4(s0, s1, s2, s3);
                    cu = nxt;
                }
            }
            bar_arrive(BAR_EMPTY(c));
        }

        // tail region: 17 chunk16s from the helper-produced global buffer
        if (lane == 0) {
            int* cbase = &g_cnt[b * NSLICE];
            const float4* c2p = reinterpret_cast<const float4*>(
                &g_cur2[b * T_TAIL]);
            float4* op = reinterpret_cast<float4*>(out_row + T_MAIN);

            // wait + prefetch chunk16 0 (slices 0,1)
            while (ld_acquire(&cbase[0]) < 4 || ld_acquire(&cbase[1]) < 4) { }
            float4 a0 = c2p[0], a1 = c2p[1], a2 = c2p[2], a3 = c2p[3];

            #pragma unroll 1
            for (int c = 0; c < T_TAIL / 16; ++c) {
                float4 n0, n1, n2, n3;
                if (c + 1 < T_TAIL / 16) {
                    while (ld_acquire(&cbase[2 * c + 2]) < 4 ||
                           ld_acquire(&cbase[2 * c + 3]) < 4) { }
                    n0 = c2p[4 * c + 4]; n1 = c2p[4 * c + 5];
                    n2 = c2p[4 * c + 6]; n3 = c2p[4 * c + 7];
                }
                float4 sA = make_float4(lif_step(v, a0.x), lif_step(v, a0.y),
                                        lif_step(v, a0.z), lif_step(v, a0.w));
                float4 sB = make_float4(lif_step(v, a1.x), lif_step(v, a1.y),
                                        lif_step(v, a1.z), lif_step(v, a1.w));
                float4 sC = make_float4(lif_step(v, a2.x), lif_step(v, a2.y),
                                        lif_step(v, a2.z), lif_step(v, a2.w));
                float4 sD = make_float4(lif_step(v, a3.x), lif_step(v, a3.y),
                                        lif_step(v, a3.z), lif_step(v, a3.w));
                op[4 * c + 0] = sA; op[4 * c + 1] = sB;
                op[4 * c + 2] = sC; op[4 * c + 3] = sD;

                cbase[2 * c] = 0; cbase[2 * c + 1] = 0;  // reset for replay
                a0 = n0; a1 = n1; a2 = n2; a3 = n3;
            }

            // final membrane potential vT
            if (out_size > B_SZ * T_SZ)
                out[B_SZ * T_SZ + b] = v;
        }
    }
}

extern "C" void kernel_launch(void* const* d_in, const int* in_sizes, int n_in,
                              void* d_out, int out_size)
{
    const float* x    = (const float*)d_in[0];  // [256, 2000, 128] fp32
    const float* W    = (const float*)d_in[1];  // [128, 1] fp32
    const float* bias = (const float*)d_in[2];  // [1] fp32
    float* out = (float*)d_out;                 // spikes [256*2000] then vT [256]

    lif_fused_kernel<<<B_SZ + HELP_BLOCKS, THREADS>>>(x, W, bias, out, out_size);
}

// round 15
// speedup vs baseline: 1.4395x; 1.4395x over previous
#include <cuda_runtime.h>

#define B_SZ 256
#define T_SZ 2000
#define F_SZ 128

#define CHUNK   128                // timesteps per pipeline chunk
#define NCHUNK  16                 // ceil(2000/128); last chunk has 80 valid
#define NBUF    4                  // smem ring depth
#define DOT_WARPS 8
#define T_PER_WARP 16              // rows per dot warp per chunk
#define NPASS   4                  // 4 rows per pass (8 lanes/row)
#define THREADS (32 * (DOT_WARPS + 1))  // 288

// BETA = sigmoid(2.0), VTH = 1.0
#define BETA_F 0.8807970779778823f

// physical barriers 0..15; __syncthreads unused, so 0 is ours.
#define BAR_FULL(i)  ((i) & 3)
#define BAR_EMPTY(i) (4 + ((i) & 3))

__device__ __forceinline__ void bar_sync(int id) {
    asm volatile("bar.sync %0, %1;" :: "r"(id), "n"(THREADS) : "memory");
}
__device__ __forceinline__ void bar_arrive(int id) {
    asm volatile("bar.arrive %0, %1;" :: "r"(id), "n"(THREADS) : "memory");
}

__device__ __forceinline__ float lif_step(float& v, float c) {
    float u = fmaf(BETA_F, v, c);
    float w = u - 1.0f;
    bool  p = (u >= 1.0f);
    v = p ? w : u;
    return p ? 1.0f : 0.0f;
}

__global__ void __launch_bounds__(THREADS, 2) lif_fused_kernel(
    const float* __restrict__ x, const float* __restrict__ W,
    const float* __restrict__ bias, float* __restrict__ out, int out_size)
{
    __shared__ float cur_s[NBUF][CHUNK];

    const int b    = blockIdx.x;          // batch row
    const int wid  = threadIdx.x >> 5;
    const int lane = threadIdx.x & 31;

    if (wid > 0) {
        // ================= producers: dot warps 1..8 =================
        const int sub = lane & 7;   // position within row (8 lanes x 16 floats)
        const int grp = lane >> 3;  // row within each 4-row pass

        float4 w4[4];
        #pragma unroll
        for (int j = 0; j < 4; ++j)
            w4[j] = reinterpret_cast<const float4*>(W)[sub + 8 * j];
        const float bias_v = bias[0];

        const int slice0 = (wid - 1) * T_PER_WARP;
        const float4* X4 = reinterpret_cast<const float4*>(
            x + (size_t)b * T_SZ * F_SZ);

        #pragma unroll 1
        for (int c = 0; c < NCHUNK; ++c) {
            const int buf = c & (NBUF - 1);
            const int t0  = c * CHUNK + slice0;

            // Phase 1: batch ALL 16 LDG.128 (8KB in flight per warp),
            // streaming hint (x is touched exactly once).
            float4 xv[NPASS][4];
            #pragma unroll
            for (int p = 0; p < NPASS; ++p) {
                int trow = t0 + p * 4 + grp;
                trow = (trow < T_SZ) ? trow : (T_SZ - 1);   // clamp tail
                const float4* rp = X4 + (size_t)trow * (F_SZ / 4) + sub;
                #pragma unroll
                for (int j = 0; j < 4; ++j)
                    xv[p][j] = __ldcs(rp + 8 * j);
            }

            bar_sync(BAR_EMPTY(c));     // ring slot free (loads stay in flight)

            // Phase 2: dot + 3-stage 8-lane butterfly per pass
            #pragma unroll
            for (int p = 0; p < NPASS; ++p) {
                float s = 0.0f;
                #pragma unroll
                for (int j = 0; j < 4; ++j) {
                    s = fmaf(xv[p][j].x, w4[j].x, s);
                    s = fmaf(xv[p][j].y, w4[j].y, s);
                    s = fmaf(xv[p][j].z, w4[j].z, s);
                    s = fmaf(xv[p][j].w, w4[j].w, s);
                }
                s += __shfl_xor_sync(0xFFFFFFFFu, s, 4);
                s += __shfl_xor_sync(0xFFFFFFFFu, s, 2);
                s += __shfl_xor_sync(0xFFFFFFFFu, s, 1);
                const int trow = t0 + p * 4 + grp;
                if (sub == 0 && trow < T_SZ)
                    cur_s[buf][trow - c * CHUNK] = s + bias_v;
            }

            bar_arrive(BAR_FULL(c));    // signal produced; roll on
        }
    } else {
        // ================= consumer: scan warp 0 =================
        #pragma unroll
        for (int i = 0; i < NBUF; ++i)
            bar_arrive(BAR_EMPTY(i));   // prime the ring

        float v = 0.0f;
        float* out_row = out + (size_t)b * T_SZ;

        for (int c = 0; c < NCHUNK; ++c) {
            bar_sync(BAR_FULL(c));      // wait for all 8 producer arrivals

            if (lane == 0) {
                const int buf   = c & (NBUF - 1);
                const int tbase = c * CHUNK;
                const int ngrp  = ((c == NCHUNK - 1) ? (T_SZ - tbase) : CHUNK) / 4;
                const float4* cs = reinterpret_cast<const float4*>(&cur_s[buf][0]);
                float4* op = reinterpret_cast<float4*>(out_row + tbase);

                float4 cu = cs[0];                      // prefetch group 0
                #pragma unroll 4
                for (int g = 0; g < ngrp; ++g) {
                    float4 nxt = cu;
                    if (g + 1 < ngrp) nxt = cs[g + 1];  // prefetch next group
                    float s0 = lif_step(v, cu.x);
                    float s1 = lif_step(v, cu.y);
                    float s2 = lif_step(v, cu.z);
                    float s3 = lif_step(v, cu.w);
                    op[g] = make_float4(s0, s1, s2, s3);
                    cu = nxt;
                }
            }

            bar_arrive(BAR_EMPTY(c));   // release ring slot
        }

        // final membrane potential vT
        if (lane == 0 && out_size > B_SZ * T_SZ)
            out[B_SZ * T_SZ + b] = v;
    }
}

extern "C" void kernel_launch(void* const* d_in, const int* in_sizes, int n_in,
                              void* d_out, int out_size)
{
    const float* x    = (const float*)d_in[0];  // [256, 2000, 128] fp32
    const float* W    = (const float*)d_in[1];  // [128, 1] fp32
    const float* bias = (const float*)d_in[2];  // [1] fp32
    float* out = (float*)d_out;                 // spikes [256*2000] then vT [256]

    lif_fused_kernel<<<B_SZ, THREADS>>>(x, W, bias, out, out_size);
}